// round 7
// baseline (speedup 1.0000x reference)
#include <cuda_runtime.h>
#include <cuda_fp16.h>
#include <math.h>
#include <stdint.h>

#define NB    2
#define NC    128
#define NH    512
#define NW    512
#define NWIN  4096
#define NWF   1228
#define NSEL  (NB*NWF)
#define NCOPY 2048
#define NMEGA (NCOPY + NSEL)
#define SCALE 0.08838834764831845f

// ---------------- static device scratch -------------------------------------
__device__ float g_score[NB*NWIN];
__device__ int   g_sel[NB*NWF];
__device__ int   g_cnt[NB];
__device__ unsigned char g_flag[NB*NWIN];
__device__ float g_gx[NB*NC*64];
__device__ __align__(16) uint2  g_wfrag[6*4096];        // fragment-major weights
__device__ __align__(16) __half g_k16[NB*64*128];       // cross-attn K row-major
__device__ __align__(16) __half g_v1t[NB*128*64];       // cross-attn V transposed

#define MAT_QG 0
#define MAT_LIN 1
#define MAT_Q2 2
#define MAT_K2 3
#define MAT_V2 4
#define MAT_PR 5

// ---------------- helpers ----------------------------------------------------
__device__ __forceinline__ uint32_t h2u(float a, float b) {
    __half2 h = __floats2half2_rn(a, b);
    return reinterpret_cast<uint32_t&>(h);
}
__device__ __forceinline__ void mma16(float* c, uint32_t a0, uint32_t a1,
                                      uint32_t a2, uint32_t a3,
                                      uint32_t b0, uint32_t b1) {
    asm volatile("mma.sync.aligned.m16n8k16.row.col.f32.f16.f16.f32 "
                 "{%0,%1,%2,%3}, {%4,%5,%6,%7}, {%8,%9}, {%0,%1,%2,%3};"
                 : "+f"(c[0]), "+f"(c[1]), "+f"(c[2]), "+f"(c[3])
                 : "r"(a0), "r"(a1), "r"(a2), "r"(a3), "r"(b0), "r"(b1));
}
#define LDSM4(r0, r1, r2, r3, addr) \
    asm volatile("ldmatrix.sync.aligned.m8n8.x4.shared.b16 {%0,%1,%2,%3}, [%4];" \
                 : "=r"(r0), "=r"(r1), "=r"(r2), "=r"(r3) : "r"(addr))
__device__ __forceinline__ uint32_t smem_u32(const void* p) {
    uint32_t a;
    asm("{ .reg .u64 t; cvta.to.shared.u64 t, %1; cvt.u32.u64 %0, t; }" : "=r"(a) : "l"(p));
    return a;
}
__device__ __forceinline__ float gelu_exact(float x) {
    return 0.5f * x * (1.0f + erff(x * 0.70710678118654752f));
}

// ---------------- prep kernels ----------------------------------------------
__global__ void wprep_kernel(const float* __restrict__ qgw, const float* __restrict__ lw,
                             const float* __restrict__ qkvw, const float* __restrict__ pw) {
    int i = blockIdx.x * 256 + threadIdx.x;          // 24576
    int mat = i >> 12, r = i & 4095;
    int kb = r >> 9, n8 = (r >> 5) & 15, lane = r & 31;
    int g = lane >> 2, t = lane & 3;
    int n = n8*8 + g, k = kb*16 + 2*t;
    const float* W = (mat == 0) ? qgw : (mat == 1) ? lw
                   : (mat <= 4) ? qkvw + (mat - 2)*16384 : pw;
    const float* row = W + n*128;
    uint2 o;
    o.x = h2u(row[k],   row[k+1]);
    o.y = h2u(row[k+8], row[k+9]);
    g_wfrag[i] = o;
}

__global__ void scores_kernel(const float* __restrict__ unc) {
    if (blockIdx.x == 0 && threadIdx.x < NB) g_cnt[threadIdx.x] = 0;
    int gw = blockIdx.x * 8 + (threadIdx.x >> 5);
    int lane = threadIdx.x & 31;
    if (gw >= NB*NWIN) return;
    if (lane == 0) g_flag[gw] = 0;
    int b = gw / NWIN, w = gw % NWIN;
    int wh = w >> 6, ww = w & 63;
    const float* base = unc + ((size_t)b*NH + wh*8)*NW + ww*8;
    int r0 = lane >> 3, c0 = lane & 7;
    double s = (double)base[r0*NW + c0] + (double)base[(r0+4)*NW + c0];
    #pragma unroll
    for (int o = 16; o; o >>= 1) s += __shfl_down_sync(0xffffffffu, s, o);
    if (lane == 0) g_score[gw] = (float)(s * (1.0/64.0));
}

__global__ void select_kernel() {
    __shared__ float s_sc[NWIN];
    int b = blockIdx.x >> 2, part = blockIdx.x & 3;
    const float* sc = g_score + b*NWIN;
    for (int i = threadIdx.x; i < NWIN; i += 1024) s_sc[i] = sc[i];
    __syncthreads();
    int w = part*1024 + threadIdx.x;
    float my = s_sc[w];
    int rank = 0;
    #pragma unroll 8
    for (int j = 0; j < NWIN; j++) {
        float v = s_sc[j];
        rank += (v > my) || (v == my && j < w);
    }
    if (rank < NWF) {
        int pos = atomicAdd(&g_cnt[b], 1);
        g_sel[b*NWF + pos] = w;
        g_flag[b*NWIN + w] = 1;
    }
}

// read-only 8x8 grid average pool
__global__ void pool_kernel(const float* __restrict__ fm) {
    __shared__ float sp[512];
    int bci = blockIdx.x, ci = bci & 7, bc = bci >> 3;
    const float* base = fm + ((size_t)bc*NH + ci*64)*NW;
    int t = threadIdx.x;
    float acc = 0.f;
    #pragma unroll 4
    for (int r = 0; r < 64; r++) acc += base[(size_t)r*NW + t];
    sp[t] = acc;
    __syncthreads();
    for (int off = 32; off >= 1; off >>= 1) {
        if ((t & 63) < off) sp[t] += sp[t + off];
        __syncthreads();
    }
    if ((t & 63) == 0) g_gx[bc*64 + ci*8 + (t >> 6)] = sp[t] * (1.0f/4096.0f);
}

// k1, v1 for cross attention -> fp16 (K row-major, V transposed)
__global__ void kv_kernel(const float* __restrict__ kvw) {
    __shared__ float sg[NC];
    int b = blockIdx.x >> 6, p = blockIdx.x & 63;
    int tid = threadIdx.x;
    int c = tid & 127;
    bool isv = tid >= 128;
    if (tid < 128) sg[tid] = g_gx[(b*NC + tid)*64 + p];
    __syncthreads();
    const float* wr = kvw + (size_t)(c + (isv ? NC : 0)) * NC;
    float a = 0.f;
    #pragma unroll 8
    for (int cc = 0; cc < NC; cc++) a = fmaf(sg[cc], wr[cc], a);
    if (!isv) g_k16[(b*64 + p)*128 + c] = __float2half(a);
    else      g_v1t[(b*128 + c)*64 + p] = __float2half(a);
}

// ---------------- fused mega kernel (copy blocks + window blocks) ------------
#define AST 136    // half stride (s_a, s_b)
#define VST 72     // half stride (s_vt)
#define WST 132    // float stride (s_wf)
#define PST 68     // float stride (s_p)
#define OFF_WF 0
#define OFF_P  33792
#define OFF_A  51200
#define OFF_B  68608
#define OFF_VT 86016
#define SMEMB  104448

// C[4][2][4] += A(64x128 @ ua) @ W^T via fragment-major weights
__device__ __forceinline__ void gemmW(uint32_t ua, const uint2* __restrict__ wfr,
                                      int lane, int wp, float C[4][2][4]) {
    #pragma unroll
    for (int mt = 0; mt < 4; mt++)
        #pragma unroll
        for (int nt = 0; nt < 2; nt++)
            #pragma unroll
            for (int k = 0; k < 4; k++) C[mt][nt][k] = 0.f;
    uint32_t ab = ua + (((lane & 15)*AST + ((lane & 16) >> 1)) << 1);
    #pragma unroll
    for (int kb = 0; kb < 8; kb++) {
        uint2 w0 = __ldg(&wfr[(kb*16 + 2*wp    )*32 + lane]);
        uint2 w1 = __ldg(&wfr[(kb*16 + 2*wp + 1)*32 + lane]);
        #pragma unroll
        for (int mt = 0; mt < 4; mt++) {
            uint32_t a0, a1, a2, a3;
            LDSM4(a0, a1, a2, a3, ab + mt*(AST*32) + kb*32);
            mma16(C[mt][0], a0, a1, a2, a3, w0.x, w0.y);
            mma16(C[mt][1], a0, a1, a2, a3, w1.x, w1.y);
        }
    }
}

// Cq[4][4] = Q(ua) @ K(ub)^T, warp strip of 8 cols
__device__ __forceinline__ void gemmQK(uint32_t ua, uint32_t ub,
                                       int lane, int wp, float Cq[4][4]) {
    #pragma unroll
    for (int mt = 0; mt < 4; mt++)
        #pragma unroll
        for (int k = 0; k < 4; k++) Cq[mt][k] = 0.f;
    uint32_t ab = ua + (((lane & 15)*AST + ((lane & 16) >> 1)) << 1);
    uint32_t bb = ub + (((wp*8 + (lane & 7))*AST + (lane >> 3)*8) << 1);
    #pragma unroll
    for (int kp = 0; kp < 4; kp++) {         // two k-steps per iter
        uint32_t b0, b1, b2, b3;
        LDSM4(b0, b1, b2, b3, bb + kp*64);
        #pragma unroll
        for (int mt = 0; mt < 4; mt++) {
            uint32_t a0, a1, a2, a3;
            LDSM4(a0, a1, a2, a3, ab + mt*(AST*32) + kp*64);
            mma16(Cq[mt], a0, a1, a2, a3, b0, b1);
            LDSM4(a0, a1, a2, a3, ab + mt*(AST*32) + kp*64 + 32);
            mma16(Cq[mt], a0, a1, a2, a3, b2, b3);
        }
    }
}

// C[4][2][4] = attn(ua cols 0..63) @ V(uvt transposed), K=64
__device__ __forceinline__ void gemmAV(uint32_t ua, uint32_t uvt,
                                       int lane, int wp, float C[4][2][4]) {
    #pragma unroll
    for (int mt = 0; mt < 4; mt++)
        #pragma unroll
        for (int nt = 0; nt < 2; nt++)
            #pragma unroll
            for (int k = 0; k < 4; k++) C[mt][nt][k] = 0.f;
    uint32_t ab = ua + (((lane & 15)*AST + ((lane & 16) >> 1)) << 1);
    uint32_t vb = uvt + (((wp*16 + (lane & 7) + ((lane & 16) >> 1))*VST + (lane & 8)) << 1);
    #pragma unroll
    for (int kb = 0; kb < 4; kb++) {
        uint32_t b0, b1, b2, b3;
        LDSM4(b0, b1, b2, b3, vb + kb*32);
        #pragma unroll
        for (int mt = 0; mt < 4; mt++) {
            uint32_t a0, a1, a2, a3;
            LDSM4(a0, a1, a2, a3, ab + mt*(AST*32) + kb*32);
            mma16(C[mt][0], a0, a1, a2, a3, b0, b1);
            mma16(C[mt][1], a0, a1, a2, a3, b2, b3);
        }
    }
}

__global__ void __launch_bounds__(256) mega_kernel(
    const float* __restrict__ fm,
    const float* __restrict__ lb, const float* __restrict__ pb,
    float* __restrict__ out)
{
    extern __shared__ char sm[];
    int tid = threadIdx.x;
    int bid = blockIdx.x;
    const size_t plane = (size_t)NH * NW;

    bool is_copy;
    int idx;
    if (bid < 2*NCOPY) { is_copy = ((bid & 1) == 0); idx = bid >> 1; }
    else               { is_copy = false; idx = NCOPY + (bid - 2*NCOPY); }

    if (is_copy) {
        // ---- copy non-selected pixels: bc = idx>>3, rows band*64..+63 ----
        unsigned char* sflag = (unsigned char*)sm;
        int bc = idx >> 3, band = idx & 7;
        int b = bc >> 7;
        const unsigned char* fl = g_flag + b*NWIN + band*8*64;
        for (int i = tid; i < 512; i += 256) sflag[i] = fl[i];
        __syncthreads();
        const float* src = fm  + ((size_t)bc*NH + band*64)*NW;
        float*       dst = out + ((size_t)bc*NH + band*64)*NW;
        #pragma unroll 2
        for (int r = 0; r < 64; r++) {
            const unsigned char* frow = sflag + (r >> 3)*64;
            if (!frow[tid >> 3])
                dst[(size_t)r*NW + tid] = src[(size_t)r*NW + tid];
            if (!frow[(tid + 256) >> 3])
                dst[(size_t)r*NW + tid + 256] = src[(size_t)r*NW + tid + 256];
        }
        return;
    }

    // ------------------- window block -------------------
    float*  s_wf = (float*) (sm + OFF_WF);
    float*  s_p  = (float*) (sm + OFF_P);
    __half* s_a  = (__half*)(sm + OFF_A);
    __half* s_b  = (__half*)(sm + OFF_B);
    __half* s_vt = (__half*)(sm + OFF_VT);
    uint32_t ua  = smem_u32(s_a);
    uint32_t ub  = smem_u32(s_b);
    uint32_t uvt = smem_u32(s_vt);

    int wp = tid >> 5, lane = tid & 31;
    int g = lane >> 2, t = lane & 3;
    int b = idx / NWF;
    int w = g_sel[idx];
    int wh = w >> 6, ww = w & 63;
    const float* fbase = fm  + (size_t)b*NC*plane + (size_t)(wh*8)*NW + ww*8;
    float*       obase = out + (size_t)b*NC*plane + (size_t)(wh*8)*NW + ww*8;

    // gather window (fp32 master + fp16 mirror) + stage k1 / v1t
    {
        int col = tid & 7, r = (tid >> 3) & 7, c0 = tid >> 6;
        int t8 = r*8 + col;
        #pragma unroll
        for (int k = 0; k < 32; k++) {
            int c = c0 + 4*k;
            float v = fbase[(size_t)c*plane + r*NW + col];
            s_wf[t8*WST + c] = v;
            s_a[t8*AST + c] = __float2half(v);
        }
        const uint4* kg = (const uint4*)(g_k16 + b*8192);
        const uint4* vg = (const uint4*)(g_v1t + b*8192);
        for (int i = tid; i < 1024; i += 256) {
            int row = i >> 4, c16 = i & 15;
            *(uint4*)(s_b + row*AST + c16*8) = kg[row*16 + c16];
        }
        for (int i = tid; i < 1024; i += 256) {
            int row = i >> 3, c8 = i & 7;
            *(uint4*)(s_vt + row*VST + c8*8) = vg[row*8 + c8];
        }
    }
    __syncthreads();

    float C[4][2][4];
    float Cq[4][4];

    #define FOR_FRAG for (int mt = 0; mt < 4; mt++) for (int nt = 0; nt < 2; nt++)
    #define R0 (mt*16 + g)
    #define R1 (mt*16 + g + 8)
    #define CL (wp*16 + nt*8 + 2*t)

    // ---- q1 = wf @ Wqg^T ----
    gemmW(ua, g_wfrag + MAT_QG*4096, lane, wp, C);
    __syncthreads();
    FOR_FRAG {
        *(uint32_t*)(s_a + R0*AST + CL) = h2u(C[mt][nt][0], C[mt][nt][1]);
        *(uint32_t*)(s_a + R1*AST + CL) = h2u(C[mt][nt][2], C[mt][nt][3]);
    }
    __syncthreads();

    // ---- logits1 = q1 @ k1^T ----
    gemmQK(ua, ub, lane, wp, Cq);
    #pragma unroll
    for (int mt = 0; mt < 4; mt++) {
        int cc = wp*8 + 2*t;
        s_p[(mt*16+g)*PST + cc]     = Cq[mt][0]*SCALE;
        s_p[(mt*16+g)*PST + cc+1]   = Cq[mt][1]*SCALE;
        s_p[(mt*16+g+8)*PST + cc]   = Cq[mt][2]*SCALE;
        s_p[(mt*16+g+8)*PST + cc+1] = Cq[mt][3]*SCALE;
    }
    __syncthreads();

    // ---- softmax1 -> s_a cols 0..63 (half) ----
    {
        int row = tid >> 2, q = tid & 3;
        float* pr = s_p + row*PST + q*16;
        float m = -1e30f, v[16];
        #pragma unroll
        for (int k = 0; k < 16; k++) { v[k] = pr[k]; m = fmaxf(m, v[k]); }
        m = fmaxf(m, __shfl_xor_sync(0xffffffffu, m, 1));
        m = fmaxf(m, __shfl_xor_sync(0xffffffffu, m, 2));
        float s = 0.f;
        #pragma unroll
        for (int k = 0; k < 16; k++) { v[k] = __expf(v[k] - m); s += v[k]; }
        s += __shfl_xor_sync(0xffffffffu, s, 1);
        s += __shfl_xor_sync(0xffffffffu, s, 2);
        float inv = 1.0f / s;
        #pragma unroll
        for (int u = 0; u < 8; u++)
            *(uint32_t*)(s_a + row*AST + q*16 + 2*u) = h2u(v[2*u]*inv, v[2*u+1]*inv);
    }
    __syncthreads();

    // ---- av1 = attn @ v1 ; wf += av1 ----
    gemmAV(ua, uvt, lane, wp, C);
    __syncthreads();
    FOR_FRAG {
        float f0 = s_wf[R0*WST + CL]   + C[mt][nt][0];
        float f1 = s_wf[R0*WST + CL+1] + C[mt][nt][1];
        float f2 = s_wf[R1*WST + CL]   + C[mt][nt][2];
        float f3 = s_wf[R1*WST + CL+1] + C[mt][nt][3];
        s_wf[R0*WST + CL] = f0; s_wf[R0*WST + CL+1] = f1;
        s_wf[R1*WST + CL] = f2; s_wf[R1*WST + CL+1] = f3;
        *(uint32_t*)(s_a + R0*AST + CL) = h2u(f0, f1);
        *(uint32_t*)(s_a + R1*AST + CL) = h2u(f2, f3);
    }
    __syncthreads();

    // ---- MLP1: wf += gelu(wf @ lw^T + lb) ----
    gemmW(ua, g_wfrag + MAT_LIN*4096, lane, wp, C);
    __syncthreads();
    FOR_FRAG {
        float b0 = __ldg(&lb[CL]), b1 = __ldg(&lb[CL+1]);
        float f0 = s_wf[R0*WST + CL]   + gelu_exact(C[mt][nt][0] + b0);
        float f1 = s_wf[R0*WST + CL+1] + gelu_exact(C[mt][nt][1] + b1);
        float f2 = s_wf[R1*WST + CL]   + gelu_exact(C[mt][nt][2] + b0);
        float f3 = s_wf[R1*WST + CL+1] + gelu_exact(C[mt][nt][3] + b1);
        s_wf[R0*WST + CL] = f0; s_wf[R0*WST + CL+1] = f1;
        s_wf[R1*WST + CL] = f2; s_wf[R1*WST + CL+1] = f3;
        *(uint32_t*)(s_a + R0*AST + CL) = h2u(f0, f1);
        *(uint32_t*)(s_a + R1*AST + CL) = h2u(f2, f3);
    }
    __syncthreads();

    // ---- self-attention projections ----
    gemmW(ua, g_wfrag + MAT_K2*4096, lane, wp, C);
    FOR_FRAG {
        *(uint32_t*)(s_b + R0*AST + CL) = h2u(C[mt][nt][0], C[mt][nt][1]);
        *(uint32_t*)(s_b + R1*AST + CL) = h2u(C[mt][nt][2], C[mt][nt][3]);
    }
    gemmW(ua, g_wfrag + MAT_V2*4096, lane, wp, C);
    FOR_FRAG {
        s_vt[(CL  )*VST + R0] = __float2half(C[mt][nt][0]);
        s_vt[(CL+1)*VST + R0] = __float2half(C[mt][nt][1]);
        s_vt[(CL  )*VST + R1] = __float2half(C[mt][nt][2]);
        s_vt[(CL+1)*VST + R1] = __float2half(C[mt][nt][3]);
    }
    gemmW(ua, g_wfrag + MAT_Q2*4096, lane, wp, C);
    __syncthreads();
    FOR_FRAG {
        *(uint32_t*)(s_a + R0*AST + CL) = h2u(C[mt][nt][0], C[mt][nt][1]);
        *(uint32_t*)(s_a + R1*AST + CL) = h2u(C[mt][nt][2], C[mt][nt][3]);
    }
    __syncthreads();

    // ---- logits2 = q2 @ k2^T ----
    gemmQK(ua, ub, lane, wp, Cq);
    #pragma unroll
    for (int mt = 0; mt < 4; mt++) {
        int cc = wp*8 + 2*t;
        s_p[(mt*16+g)*PST + cc]     = Cq[mt][0]*SCALE;
        s_p[(mt*16+g)*PST + cc+1]   = Cq[mt][1]*SCALE;
        s_p[(mt*16+g+8)*PST + cc]   = Cq[mt][2]*SCALE;
        s_p[(mt*16+g+8)*PST + cc+1] = Cq[mt][3]*SCALE;
    }
    __syncthreads();
    {
        int row = tid >> 2, q = tid & 3;
        float* pr = s_p + row*PST + q*16;
        float m = -1e30f, v[16];
        #pragma unroll
        for (int k = 0; k < 16; k++) { v[k] = pr[k]; m = fmaxf(m, v[k]); }
        m = fmaxf(m, __shfl_xor_sync(0xffffffffu, m, 1));
        m = fmaxf(m, __shfl_xor_sync(0xffffffffu, m, 2));
        float s = 0.f;
        #pragma unroll
        for (int k = 0; k < 16; k++) { v[k] = __expf(v[k] - m); s += v[k]; }
        s += __shfl_xor_sync(0xffffffffu, s, 1);
        s += __shfl_xor_sync(0xffffffffu, s, 2);
        float inv = 1.0f / s;
        #pragma unroll
        for (int u = 0; u < 8; u++)
            *(uint32_t*)(s_a + row*AST + q*16 + 2*u) = h2u(v[2*u]*inv, v[2*u+1]*inv);
    }
    __syncthreads();

    // ---- av2 = attn @ v2 -> s_b (half) ----
    gemmAV(ua, uvt, lane, wp, C);
    FOR_FRAG {
        *(uint32_t*)(s_b + R0*AST + CL) = h2u(C[mt][nt][0], C[mt][nt][1]);
        *(uint32_t*)(s_b + R1*AST + CL) = h2u(C[mt][nt][2], C[mt][nt][3]);
    }
    __syncthreads();

    // ---- scrambled residual: wf[i][j] += av[j%64][2i + j/64] ----
    #pragma unroll
    for (int k = 0; k < 32; k++) {
        int id2 = tid + 256*k;
        int i = id2 >> 7, j = id2 & 127;
        float f = s_wf[i*WST + j] + __half2float(s_b[(j & 63)*AST + 2*i + (j >> 6)]);
        s_wf[i*WST + j] = f;
        s_a[i*AST + j] = __float2half(f);
    }
    __syncthreads();

    // ---- MLP2: wf += gelu(wf @ pw^T + pb) ----
    gemmW(ua, g_wfrag + MAT_PR*4096, lane, wp, C);
    __syncthreads();
    FOR_FRAG {
        float b0 = __ldg(&pb[CL]), b1 = __ldg(&pb[CL+1]);
        s_wf[R0*WST + CL]   += gelu_exact(C[mt][nt][0] + b0);
        s_wf[R0*WST + CL+1] += gelu_exact(C[mt][nt][1] + b1);
        s_wf[R1*WST + CL]   += gelu_exact(C[mt][nt][2] + b0);
        s_wf[R1*WST + CL+1] += gelu_exact(C[mt][nt][3] + b1);
    }
    __syncthreads();

    // ---- scatter ----
    {
        int col = tid & 7, r = (tid >> 3) & 7, c0 = tid >> 6;
        int t8 = r*8 + col;
        #pragma unroll
        for (int k = 0; k < 32; k++) {
            int c = c0 + 4*k;
            obase[(size_t)c*plane + r*NW + col] = s_wf[t8*WST + c];
        }
    }
    #undef FOR_FRAG
    #undef R0
    #undef R1
    #undef CL
}

// ---------------- launch ------------------------------------------------------
extern "C" void kernel_launch(void* const* d_in, const int* in_sizes, int n_in,
                              void* d_out, int out_size) {
    const float* fm   = (const float*)d_in[0];
    const float* unc  = (const float*)d_in[1];
    const float* qgw  = (const float*)d_in[2];
    const float* kvw  = (const float*)d_in[3];
    const float* lw   = (const float*)d_in[4];
    const float* lb   = (const float*)d_in[5];
    const float* qkvw = (const float*)d_in[6];
    const float* pw   = (const float*)d_in[7];
    const float* pb   = (const float*)d_in[8];
    float* out = (float*)d_out;

    cudaFuncSetAttribute(mega_kernel,
                         cudaFuncAttributeMaxDynamicSharedMemorySize, SMEMB);

    wprep_kernel<<<96, 256>>>(qgw, lw, qkvw, pw);
    scores_kernel<<<1024, 256>>>(unc);
    select_kernel<<<8, 1024>>>();
    pool_kernel<<<NB*NC*8, 512>>>(fm);
    kv_kernel<<<NB*64, 256>>>(kvw);
    mega_kernel<<<NMEGA, 256, SMEMB>>>(fm, lb, pb, out);
}

// round 8
// speedup vs baseline: 1.2014x; 1.2014x over previous
#include <cuda_runtime.h>
#include <cuda_fp16.h>
#include <math.h>
#include <stdint.h>

#define NB    2
#define NC    128
#define NH    512
#define NW    512
#define NWIN  4096
#define NWF   1228
#define NSEL  (NB*NWF)
#define SCALE 0.08838834764831845f

// ---------------- static device scratch -------------------------------------
__device__ float g_score[NB*NWIN];
__device__ int   g_sel[NB*NWF];
__device__ int   g_cnt[NB];
__device__ float g_gx[NB*NC*64];
__device__ __align__(16) uint2  g_wfrag[6*4096];        // fragment-major weights
__device__ __align__(16) __half g_k16[NB*64*128];       // cross-attn K row-major
__device__ __align__(16) __half g_v1t[NB*128*64];       // cross-attn V transposed

#define MAT_QG 0
#define MAT_LIN 1
#define MAT_Q2 2
#define MAT_K2 3
#define MAT_V2 4
#define MAT_PR 5

// ---------------- helpers ----------------------------------------------------
__device__ __forceinline__ uint32_t h2u(float a, float b) {
    __half2 h = __floats2half2_rn(a, b);
    return reinterpret_cast<uint32_t&>(h);
}
__device__ __forceinline__ void mma16(float* c, uint32_t a0, uint32_t a1,
                                      uint32_t a2, uint32_t a3,
                                      uint32_t b0, uint32_t b1) {
    asm volatile("mma.sync.aligned.m16n8k16.row.col.f32.f16.f16.f32 "
                 "{%0,%1,%2,%3}, {%4,%5,%6,%7}, {%8,%9}, {%0,%1,%2,%3};"
                 : "+f"(c[0]), "+f"(c[1]), "+f"(c[2]), "+f"(c[3])
                 : "r"(a0), "r"(a1), "r"(a2), "r"(a3), "r"(b0), "r"(b1));
}
#define LDSM4(r0, r1, r2, r3, addr) \
    asm volatile("ldmatrix.sync.aligned.m8n8.x4.shared.b16 {%0,%1,%2,%3}, [%4];" \
                 : "=r"(r0), "=r"(r1), "=r"(r2), "=r"(r3) : "r"(addr))
__device__ __forceinline__ uint32_t smem_u32(const void* p) {
    uint32_t a;
    asm("{ .reg .u64 t; cvta.to.shared.u64 t, %1; cvt.u32.u64 %0, t; }" : "=r"(a) : "l"(p));
    return a;
}
__device__ __forceinline__ float gelu_exact(float x) {
    return 0.5f * x * (1.0f + erff(x * 0.70710678118654752f));
}

// ---------------- prep kernels ----------------------------------------------
__global__ void wprep_kernel(const float* __restrict__ qgw, const float* __restrict__ lw,
                             const float* __restrict__ qkvw, const float* __restrict__ pw) {
    int i = blockIdx.x * 256 + threadIdx.x;          // 24576
    int mat = i >> 12, r = i & 4095;
    int kb = r >> 9, n8 = (r >> 5) & 15, lane = r & 31;
    int g = lane >> 2, t = lane & 3;
    int n = n8*8 + g, k = kb*16 + 2*t;
    const float* W = (mat == 0) ? qgw : (mat == 1) ? lw
                   : (mat <= 4) ? qkvw + (mat - 2)*16384 : pw;
    const float* row = W + n*128;
    uint2 o;
    o.x = h2u(row[k],   row[k+1]);
    o.y = h2u(row[k+8], row[k+9]);
    g_wfrag[i] = o;
}

__global__ void scores_kernel(const float* __restrict__ unc) {
    if (blockIdx.x == 0 && threadIdx.x < NB) g_cnt[threadIdx.x] = 0;
    int gw = blockIdx.x * 8 + (threadIdx.x >> 5);
    int lane = threadIdx.x & 31;
    if (gw >= NB*NWIN) return;
    int b = gw / NWIN, w = gw % NWIN;
    int wh = w >> 6, ww = w & 63;
    const float* base = unc + ((size_t)b*NH + wh*8)*NW + ww*8;
    int r0 = lane >> 3, c0 = lane & 7;
    double s = (double)base[r0*NW + c0] + (double)base[(r0+4)*NW + c0];
    #pragma unroll
    for (int o = 16; o; o >>= 1) s += __shfl_down_sync(0xffffffffu, s, o);
    if (lane == 0) g_score[gw] = (float)(s * (1.0/64.0));
}

__global__ void select_kernel() {
    __shared__ float s_sc[NWIN];
    int b = blockIdx.x >> 2, part = blockIdx.x & 3;
    const float* sc = g_score + b*NWIN;
    for (int i = threadIdx.x; i < NWIN; i += 1024) s_sc[i] = sc[i];
    __syncthreads();
    int w = part*1024 + threadIdx.x;
    float my = s_sc[w];
    int rank = 0;
    #pragma unroll 8
    for (int j = 0; j < NWIN; j++) {
        float v = s_sc[j];
        rank += (v > my) || (v == my && j < w);
    }
    if (rank < NWF) {
        int pos = atomicAdd(&g_cnt[b], 1);
        g_sel[b*NWF + pos] = w;
    }
}

// fused copy + 8x8 grid average pool (reads fm once)
__global__ void copy_pool_kernel(const float* __restrict__ fm, float* __restrict__ out) {
    __shared__ float sp[512];
    int bci = blockIdx.x, ci = bci & 7, bc = bci >> 3;
    const float* base = fm  + ((size_t)bc*NH + ci*64)*NW;
    float*       ob   = out + ((size_t)bc*NH + ci*64)*NW;
    int t = threadIdx.x;
    float acc = 0.f;
    #pragma unroll 4
    for (int r = 0; r < 64; r++) {
        float v = base[(size_t)r*NW + t];
        ob[(size_t)r*NW + t] = v;
        acc += v;
    }
    sp[t] = acc;
    __syncthreads();
    for (int off = 32; off >= 1; off >>= 1) {
        if ((t & 63) < off) sp[t] += sp[t + off];
        __syncthreads();
    }
    if ((t & 63) == 0) g_gx[bc*64 + ci*8 + (t >> 6)] = sp[t] * (1.0f/4096.0f);
}

// k1, v1 for cross attention -> fp16 (K row-major, V transposed)
__global__ void kv_kernel(const float* __restrict__ kvw) {
    __shared__ float sg[NC];
    int b = blockIdx.x >> 6, p = blockIdx.x & 63;
    int tid = threadIdx.x;
    int c = tid & 127;
    bool isv = tid >= 128;
    if (tid < 128) sg[tid] = g_gx[(b*NC + tid)*64 + p];
    __syncthreads();
    const float* wr = kvw + (size_t)(c + (isv ? NC : 0)) * NC;
    float a = 0.f;
    #pragma unroll 8
    for (int cc = 0; cc < NC; cc++) a = fmaf(sg[cc], wr[cc], a);
    if (!isv) g_k16[(b*64 + p)*128 + c] = __float2half(a);
    else      g_v1t[(b*128 + c)*64 + p] = __float2half(a);
}

// ---------------- fused window kernel ----------------------------------------
#define AST 136    // half stride (s_a, s_b)
#define VST 72     // half stride (s_vt)
#define WST 132    // float stride (s_wf)
#define PST 68     // float stride (s_p)
#define OFF_WF 0
#define OFF_P  33792
#define OFF_A  51200
#define OFF_B  68608
#define OFF_VT 86016
#define SMEMB  104448

// C[4][2][4] = A(64x128 @ ua) @ W^T via fragment-major weights
__device__ __forceinline__ void gemmW(uint32_t ua, const uint2* __restrict__ wfr,
                                      int lane, int wp, float C[4][2][4]) {
    #pragma unroll
    for (int mt = 0; mt < 4; mt++)
        #pragma unroll
        for (int nt = 0; nt < 2; nt++)
            #pragma unroll
            for (int k = 0; k < 4; k++) C[mt][nt][k] = 0.f;
    uint32_t ab = ua + (((lane & 15)*AST + ((lane & 16) >> 1)) << 1);
    #pragma unroll
    for (int kb = 0; kb < 8; kb++) {
        uint2 w0 = __ldg(&wfr[(kb*16 + 2*wp    )*32 + lane]);
        uint2 w1 = __ldg(&wfr[(kb*16 + 2*wp + 1)*32 + lane]);
        #pragma unroll
        for (int mt = 0; mt < 4; mt++) {
            uint32_t a0, a1, a2, a3;
            LDSM4(a0, a1, a2, a3, ab + mt*(AST*32) + kb*32);
            mma16(C[mt][0], a0, a1, a2, a3, w0.x, w0.y);
            mma16(C[mt][1], a0, a1, a2, a3, w1.x, w1.y);
        }
    }
}

// Cq[4][4] = Q(ua) @ K(ub)^T, warp strip of 8 cols
__device__ __forceinline__ void gemmQK(uint32_t ua, uint32_t ub,
                                       int lane, int wp, float Cq[4][4]) {
    #pragma unroll
    for (int mt = 0; mt < 4; mt++)
        #pragma unroll
        for (int k = 0; k < 4; k++) Cq[mt][k] = 0.f;
    uint32_t ab = ua + (((lane & 15)*AST + ((lane & 16) >> 1)) << 1);
    uint32_t bb = ub + (((wp*8 + (lane & 7))*AST + (lane >> 3)*8) << 1);
    #pragma unroll
    for (int kp = 0; kp < 4; kp++) {         // two k-steps per iter
        uint32_t b0, b1, b2, b3;
        LDSM4(b0, b1, b2, b3, bb + kp*64);
        #pragma unroll
        for (int mt = 0; mt < 4; mt++) {
            uint32_t a0, a1, a2, a3;
            LDSM4(a0, a1, a2, a3, ab + mt*(AST*32) + kp*64);
            mma16(Cq[mt], a0, a1, a2, a3, b0, b1);
            LDSM4(a0, a1, a2, a3, ab + mt*(AST*32) + kp*64 + 32);
            mma16(Cq[mt], a0, a1, a2, a3, b2, b3);
        }
    }
}

// C[4][2][4] = attn(ua cols 0..63) @ V(uvt transposed), K=64
__device__ __forceinline__ void gemmAV(uint32_t ua, uint32_t uvt,
                                       int lane, int wp, float C[4][2][4]) {
    #pragma unroll
    for (int mt = 0; mt < 4; mt++)
        #pragma unroll
        for (int nt = 0; nt < 2; nt++)
            #pragma unroll
            for (int k = 0; k < 4; k++) C[mt][nt][k] = 0.f;
    uint32_t ab = ua + (((lane & 15)*AST + ((lane & 16) >> 1)) << 1);
    uint32_t vb = uvt + (((wp*16 + (lane & 7) + ((lane & 16) >> 1))*VST + (lane & 8)) << 1);
    #pragma unroll
    for (int kb = 0; kb < 4; kb++) {
        uint32_t b0, b1, b2, b3;
        LDSM4(b0, b1, b2, b3, vb + kb*32);
        #pragma unroll
        for (int mt = 0; mt < 4; mt++) {
            uint32_t a0, a1, a2, a3;
            LDSM4(a0, a1, a2, a3, ab + mt*(AST*32) + kb*32);
            mma16(C[mt][0], a0, a1, a2, a3, b0, b1);
            mma16(C[mt][1], a0, a1, a2, a3, b2, b3);
        }
    }
}

__global__ void __launch_bounds__(256) window_kernel(
    const float* __restrict__ fm,
    const float* __restrict__ lb, const float* __restrict__ pb,
    float* __restrict__ out)
{
    extern __shared__ char sm[];
    float*  s_wf = (float*) (sm + OFF_WF);
    float*  s_p  = (float*) (sm + OFF_P);
    __half* s_a  = (__half*)(sm + OFF_A);
    __half* s_b  = (__half*)(sm + OFF_B);
    __half* s_vt = (__half*)(sm + OFF_VT);
    uint32_t ua  = smem_u32(s_a);
    uint32_t ub  = smem_u32(s_b);
    uint32_t uvt = smem_u32(s_vt);

    int tid = threadIdx.x, wp = tid >> 5, lane = tid & 31;
    int g = lane >> 2, t = lane & 3;
    int idx = blockIdx.x;
    int b = idx / NWF;
    int w = g_sel[idx];
    int wh = w >> 6, ww = w & 63;
    const size_t plane = (size_t)NH * NW;
    const float* fbase = fm  + (size_t)b*NC*plane + (size_t)(wh*8)*NW + ww*8;
    float*       obase = out + (size_t)b*NC*plane + (size_t)(wh*8)*NW + ww*8;

    // gather window (fp32 master + fp16 mirror) + stage k1 / v1t
    {
        int col = tid & 7, r = (tid >> 3) & 7, c0 = tid >> 6;
        int t8 = r*8 + col;
        #pragma unroll
        for (int k = 0; k < 32; k++) {
            int c = c0 + 4*k;
            float v = fbase[(size_t)c*plane + r*NW + col];
            s_wf[t8*WST + c] = v;
            s_a[t8*AST + c] = __float2half(v);
        }
        const uint4* kg = (const uint4*)(g_k16 + b*8192);
        const uint4* vg = (const uint4*)(g_v1t + b*8192);
        for (int i = tid; i < 1024; i += 256) {
            int row = i >> 4, c16 = i & 15;
            *(uint4*)(s_b + row*AST + c16*8) = kg[row*16 + c16];
        }
        for (int i = tid; i < 1024; i += 256) {
            int row = i >> 3, c8 = i & 7;
            *(uint4*)(s_vt + row*VST + c8*8) = vg[row*8 + c8];
        }
    }
    __syncthreads();

    float C[4][2][4];
    float Cq[4][4];

    #define FOR_FRAG for (int mt = 0; mt < 4; mt++) for (int nt = 0; nt < 2; nt++)
    #define R0 (mt*16 + g)
    #define R1 (mt*16 + g + 8)
    #define CL (wp*16 + nt*8 + 2*t)

    // ---- q1 = wf @ Wqg^T ----
    gemmW(ua, g_wfrag + MAT_QG*4096, lane, wp, C);
    __syncthreads();
    FOR_FRAG {
        *(uint32_t*)(s_a + R0*AST + CL) = h2u(C[mt][nt][0], C[mt][nt][1]);
        *(uint32_t*)(s_a + R1*AST + CL) = h2u(C[mt][nt][2], C[mt][nt][3]);
    }
    __syncthreads();

    // ---- logits1 = q1 @ k1^T ----
    gemmQK(ua, ub, lane, wp, Cq);
    #pragma unroll
    for (int mt = 0; mt < 4; mt++) {
        int cc = wp*8 + 2*t;
        s_p[(mt*16+g)*PST + cc]     = Cq[mt][0]*SCALE;
        s_p[(mt*16+g)*PST + cc+1]   = Cq[mt][1]*SCALE;
        s_p[(mt*16+g+8)*PST + cc]   = Cq[mt][2]*SCALE;
        s_p[(mt*16+g+8)*PST + cc+1] = Cq[mt][3]*SCALE;
    }
    __syncthreads();

    // ---- softmax1 -> s_a cols 0..63 (half) ----
    {
        int row = tid >> 2, q = tid & 3;
        float* pr = s_p + row*PST + q*16;
        float m = -1e30f, v[16];
        #pragma unroll
        for (int k = 0; k < 16; k++) { v[k] = pr[k]; m = fmaxf(m, v[k]); }
        m = fmaxf(m, __shfl_xor_sync(0xffffffffu, m, 1));
        m = fmaxf(m, __shfl_xor_sync(0xffffffffu, m, 2));
        float s = 0.f;
        #pragma unroll
        for (int k = 0; k < 16; k++) { v[k] = __expf(v[k] - m); s += v[k]; }
        s += __shfl_xor_sync(0xffffffffu, s, 1);
        s += __shfl_xor_sync(0xffffffffu, s, 2);
        float inv = 1.0f / s;
        #pragma unroll
        for (int u = 0; u < 8; u++)
            *(uint32_t*)(s_a + row*AST + q*16 + 2*u) = h2u(v[2*u]*inv, v[2*u+1]*inv);
    }
    __syncthreads();

    // ---- av1 = attn @ v1 ; wf += av1 ----
    gemmAV(ua, uvt, lane, wp, C);
    __syncthreads();
    FOR_FRAG {
        float f0 = s_wf[R0*WST + CL]   + C[mt][nt][0];
        float f1 = s_wf[R0*WST + CL+1] + C[mt][nt][1];
        float f2 = s_wf[R1*WST + CL]   + C[mt][nt][2];
        float f3 = s_wf[R1*WST + CL+1] + C[mt][nt][3];
        s_wf[R0*WST + CL] = f0; s_wf[R0*WST + CL+1] = f1;
        s_wf[R1*WST + CL] = f2; s_wf[R1*WST + CL+1] = f3;
        *(uint32_t*)(s_a + R0*AST + CL) = h2u(f0, f1);
        *(uint32_t*)(s_a + R1*AST + CL) = h2u(f2, f3);
    }
    __syncthreads();

    // ---- MLP1: wf += gelu(wf @ lw^T + lb) ----
    gemmW(ua, g_wfrag + MAT_LIN*4096, lane, wp, C);
    __syncthreads();
    FOR_FRAG {
        float b0 = __ldg(&lb[CL]), b1 = __ldg(&lb[CL+1]);
        float f0 = s_wf[R0*WST + CL]   + gelu_exact(C[mt][nt][0] + b0);
        float f1 = s_wf[R0*WST + CL+1] + gelu_exact(C[mt][nt][1] + b1);
        float f2 = s_wf[R1*WST + CL]   + gelu_exact(C[mt][nt][2] + b0);
        float f3 = s_wf[R1*WST + CL+1] + gelu_exact(C[mt][nt][3] + b1);
        s_wf[R0*WST + CL] = f0; s_wf[R0*WST + CL+1] = f1;
        s_wf[R1*WST + CL] = f2; s_wf[R1*WST + CL+1] = f3;
        *(uint32_t*)(s_a + R0*AST + CL) = h2u(f0, f1);
        *(uint32_t*)(s_a + R1*AST + CL) = h2u(f2, f3);
    }
    __syncthreads();

    // ---- self-attention projections ----
    gemmW(ua, g_wfrag + MAT_K2*4096, lane, wp, C);
    FOR_FRAG {
        *(uint32_t*)(s_b + R0*AST + CL) = h2u(C[mt][nt][0], C[mt][nt][1]);
        *(uint32_t*)(s_b + R1*AST + CL) = h2u(C[mt][nt][2], C[mt][nt][3]);
    }
    gemmW(ua, g_wfrag + MAT_V2*4096, lane, wp, C);
    FOR_FRAG {
        s_vt[(CL  )*VST + R0] = __float2half(C[mt][nt][0]);
        s_vt[(CL+1)*VST + R0] = __float2half(C[mt][nt][1]);
        s_vt[(CL  )*VST + R1] = __float2half(C[mt][nt][2]);
        s_vt[(CL+1)*VST + R1] = __float2half(C[mt][nt][3]);
    }
    gemmW(ua, g_wfrag + MAT_Q2*4096, lane, wp, C);
    __syncthreads();
    FOR_FRAG {
        *(uint32_t*)(s_a + R0*AST + CL) = h2u(C[mt][nt][0], C[mt][nt][1]);
        *(uint32_t*)(s_a + R1*AST + CL) = h2u(C[mt][nt][2], C[mt][nt][3]);
    }
    __syncthreads();

    // ---- logits2 = q2 @ k2^T ----
    gemmQK(ua, ub, lane, wp, Cq);
    #pragma unroll
    for (int mt = 0; mt < 4; mt++) {
        int cc = wp*8 + 2*t;
        s_p[(mt*16+g)*PST + cc]     = Cq[mt][0]*SCALE;
        s_p[(mt*16+g)*PST + cc+1]   = Cq[mt][1]*SCALE;
        s_p[(mt*16+g+8)*PST + cc]   = Cq[mt][2]*SCALE;
        s_p[(mt*16+g+8)*PST + cc+1] = Cq[mt][3]*SCALE;
    }
    __syncthreads();
    {
        int row = tid >> 2, q = tid & 3;
        float* pr = s_p + row*PST + q*16;
        float m = -1e30f, v[16];
        #pragma unroll
        for (int k = 0; k < 16; k++) { v[k] = pr[k]; m = fmaxf(m, v[k]); }
        m = fmaxf(m, __shfl_xor_sync(0xffffffffu, m, 1));
        m = fmaxf(m, __shfl_xor_sync(0xffffffffu, m, 2));
        float s = 0.f;
        #pragma unroll
        for (int k = 0; k < 16; k++) { v[k] = __expf(v[k] - m); s += v[k]; }
        s += __shfl_xor_sync(0xffffffffu, s, 1);
        s += __shfl_xor_sync(0xffffffffu, s, 2);
        float inv = 1.0f / s;
        #pragma unroll
        for (int u = 0; u < 8; u++)
            *(uint32_t*)(s_a + row*AST + q*16 + 2*u) = h2u(v[2*u]*inv, v[2*u+1]*inv);
    }
    __syncthreads();

    // ---- av2 = attn @ v2 -> s_b (half) ----
    gemmAV(ua, uvt, lane, wp, C);
    FOR_FRAG {
        *(uint32_t*)(s_b + R0*AST + CL) = h2u(C[mt][nt][0], C[mt][nt][1]);
        *(uint32_t*)(s_b + R1*AST + CL) = h2u(C[mt][nt][2], C[mt][nt][3]);
    }
    __syncthreads();

    // ---- scrambled residual: wf[i][j] += av[j%64][2i + j/64] ----
    #pragma unroll
    for (int k = 0; k < 32; k++) {
        int id2 = tid + 256*k;
        int i = id2 >> 7, j = id2 & 127;
        float f = s_wf[i*WST + j] + __half2float(s_b[(j & 63)*AST + 2*i + (j >> 6)]);
        s_wf[i*WST + j] = f;
        s_a[i*AST + j] = __float2half(f);
    }
    __syncthreads();

    // ---- MLP2: wf += gelu(wf @ pw^T + pb) ----
    gemmW(ua, g_wfrag + MAT_PR*4096, lane, wp, C);
    __syncthreads();
    FOR_FRAG {
        float b0 = __ldg(&pb[CL]), b1 = __ldg(&pb[CL+1]);
        s_wf[R0*WST + CL]   += gelu_exact(C[mt][nt][0] + b0);
        s_wf[R0*WST + CL+1] += gelu_exact(C[mt][nt][1] + b1);
        s_wf[R1*WST + CL]   += gelu_exact(C[mt][nt][2] + b0);
        s_wf[R1*WST + CL+1] += gelu_exact(C[mt][nt][3] + b1);
    }
    __syncthreads();

    // ---- scatter ----
    {
        int col = tid & 7, r = (tid >> 3) & 7, c0 = tid >> 6;
        int t8 = r*8 + col;
        #pragma unroll
        for (int k = 0; k < 32; k++) {
            int c = c0 + 4*k;
            obase[(size_t)c*plane + r*NW + col] = s_wf[t8*WST + c];
        }
    }
    #undef FOR_FRAG
    #undef R0
    #undef R1
    #undef CL
}

// ---------------- launch ------------------------------------------------------
extern "C" void kernel_launch(void* const* d_in, const int* in_sizes, int n_in,
                              void* d_out, int out_size) {
    const float* fm   = (const float*)d_in[0];
    const float* unc  = (const float*)d_in[1];
    const float* qgw  = (const float*)d_in[2];
    const float* kvw  = (const float*)d_in[3];
    const float* lw   = (const float*)d_in[4];
    const float* lb   = (const float*)d_in[5];
    const float* qkvw = (const float*)d_in[6];
    const float* pw   = (const float*)d_in[7];
    const float* pb   = (const float*)d_in[8];
    float* out = (float*)d_out;

    cudaFuncSetAttribute(window_kernel,
                         cudaFuncAttributeMaxDynamicSharedMemorySize, SMEMB);

    wprep_kernel<<<96, 256>>>(qgw, lw, qkvw, pw);
    scores_kernel<<<1024, 256>>>(unc);
    select_kernel<<<8, 1024>>>();
    copy_pool_kernel<<<NB*NC*8, 512>>>(fm, out);
    kv_kernel<<<NB*64, 256>>>(kvw);
    window_kernel<<<NSEL, 256, SMEMB>>>(fm, lb, pb, out);
}

// round 9
// speedup vs baseline: 1.2019x; 1.0004x over previous
#include <cuda_runtime.h>
#include <cuda_fp16.h>
#include <math.h>
#include <stdint.h>

#define NB    2
#define NC    128
#define NH    512
#define NW    512
#define NWIN  4096
#define NWF   1228
#define NSEL  (NB*NWF)
#define SCALE 0.08838834764831845f

// ---------------- static device scratch -------------------------------------
__device__ float g_score[NB*NWIN];
__device__ int   g_sel[NB*NWF];
__device__ int   g_cnt[NB];
__device__ float g_gx[NB*NC*64];
__device__ __align__(16) uint2  g_wfrag[6*4096];        // fragment-major weights
__device__ __align__(16) __half g_k16[NB*64*128];       // cross-attn K row-major
__device__ __align__(16) __half g_v1t[NB*128*64];       // cross-attn V transposed

#define MAT_QG 0
#define MAT_LIN 1
#define MAT_Q2 2
#define MAT_K2 3
#define MAT_V2 4
#define MAT_PR 5

// ---------------- helpers ----------------------------------------------------
__device__ __forceinline__ uint32_t h2u(float a, float b) {
    __half2 h = __floats2half2_rn(a, b);
    return reinterpret_cast<uint32_t&>(h);
}
__device__ __forceinline__ void mma16(float* c, uint32_t a0, uint32_t a1,
                                      uint32_t a2, uint32_t a3,
                                      uint32_t b0, uint32_t b1) {
    asm volatile("mma.sync.aligned.m16n8k16.row.col.f32.f16.f16.f32 "
                 "{%0,%1,%2,%3}, {%4,%5,%6,%7}, {%8,%9}, {%0,%1,%2,%3};"
                 : "+f"(c[0]), "+f"(c[1]), "+f"(c[2]), "+f"(c[3])
                 : "r"(a0), "r"(a1), "r"(a2), "r"(a3), "r"(b0), "r"(b1));
}
#define LDSM4(r0, r1, r2, r3, addr) \
    asm volatile("ldmatrix.sync.aligned.m8n8.x4.shared.b16 {%0,%1,%2,%3}, [%4];" \
                 : "=r"(r0), "=r"(r1), "=r"(r2), "=r"(r3) : "r"(addr))
__device__ __forceinline__ uint32_t smem_u32(const void* p) {
    uint32_t a;
    asm("{ .reg .u64 t; cvta.to.shared.u64 t, %1; cvt.u32.u64 %0, t; }" : "=r"(a) : "l"(p));
    return a;
}
// fast GELU: 0.5x(1+tanh(0.79788456x + 0.03567741x^3)) with HW tanh
__device__ __forceinline__ float gelu_fast(float x) {
    float u = fmaf(0.0356774081f * x, x * x, 0.7978845608f * x);
    float th;
    asm("tanh.approx.f32 %0, %1;" : "=f"(th) : "f"(u));
    return 0.5f * x * (1.0f + th);
}

// ---------------- prep kernels ----------------------------------------------
__global__ void wprep_kernel(const float* __restrict__ qgw, const float* __restrict__ lw,
                             const float* __restrict__ qkvw, const float* __restrict__ pw) {
    int i = blockIdx.x * 256 + threadIdx.x;          // 24576
    int mat = i >> 12, r = i & 4095;
    int kb = r >> 9, n8 = (r >> 5) & 15, lane = r & 31;
    int g = lane >> 2, t = lane & 3;
    int n = n8*8 + g, k = kb*16 + 2*t;
    const float* W = (mat == 0) ? qgw : (mat == 1) ? lw
                   : (mat <= 4) ? qkvw + (mat - 2)*16384 : pw;
    const float* row = W + n*128;
    uint2 o;
    o.x = h2u(row[k],   row[k+1]);
    o.y = h2u(row[k+8], row[k+9]);
    g_wfrag[i] = o;
}

__global__ void scores_kernel(const float* __restrict__ unc) {
    if (blockIdx.x == 0 && threadIdx.x < NB) g_cnt[threadIdx.x] = 0;
    int gw = blockIdx.x * 8 + (threadIdx.x >> 5);
    int lane = threadIdx.x & 31;
    if (gw >= NB*NWIN) return;
    int b = gw / NWIN, w = gw % NWIN;
    int wh = w >> 6, ww = w & 63;
    const float* base = unc + ((size_t)b*NH + wh*8)*NW + ww*8;
    int r0 = lane >> 3, c0 = lane & 7;
    double s = (double)base[r0*NW + c0] + (double)base[(r0+4)*NW + c0];
    #pragma unroll
    for (int o = 16; o; o >>= 1) s += __shfl_down_sync(0xffffffffu, s, o);
    if (lane == 0) g_score[gw] = (float)(s * (1.0/64.0));
}

__global__ void select_kernel() {
    __shared__ float s_sc[NWIN];
    int b = blockIdx.x >> 2, part = blockIdx.x & 3;
    const float* sc = g_score + b*NWIN;
    for (int i = threadIdx.x; i < NWIN; i += 1024) s_sc[i] = sc[i];
    __syncthreads();
    int w = part*1024 + threadIdx.x;
    float my = s_sc[w];
    int rank = 0;
    #pragma unroll 8
    for (int j = 0; j < NWIN; j++) {
        float v = s_sc[j];
        rank += (v > my) || (v == my && j < w);
    }
    if (rank < NWF) {
        int pos = atomicAdd(&g_cnt[b], 1);
        g_sel[b*NWF + pos] = w;
    }
}

// fused copy + 8x8 grid average pool, float4 (reads fm once)
__global__ void copy_pool_kernel(const float4* __restrict__ fm4, float4* __restrict__ out4) {
    __shared__ float sp[512];
    int bci = blockIdx.x, ci = bci & 7, bc = bci >> 3;
    const float4* base = fm4  + ((size_t)bc*NH + ci*64)*(NW/4);
    float4*       ob   = out4 + ((size_t)bc*NH + ci*64)*(NW/4);
    int t = threadIdx.x;
    float acc = 0.f;
    #pragma unroll 4
    for (int it = 0; it < 16; it++) {
        int i4 = it*512 + t;        // row = it*4 + (t>>7), col4 = t & 127
        float4 v = base[i4];
        ob[i4] = v;
        acc += (v.x + v.y) + (v.z + v.w);
    }
    // colband cell = (t&127)>>4 ; unique sub-slot = (t>>7)*16 + (t&15)
    int cell = (t & 127) >> 4;
    int sub  = (t >> 7) * 16 + (t & 15);
    sp[cell*64 + sub] = acc;
    __syncthreads();
    int grp = t >> 6, i = t & 63;
    for (int off = 32; off >= 1; off >>= 1) {
        if (i < off) sp[grp*64 + i] += sp[grp*64 + i + off];
        __syncthreads();
    }
    if (i == 0) g_gx[bc*64 + ci*8 + grp] = sp[grp*64] * (1.0f/4096.0f);
}

// k1, v1 for cross attention: 16 blocks, g staged in smem once
__global__ void kv_kernel(const float* __restrict__ kvw) {
    __shared__ float sg[128][65];
    int b = blockIdx.x >> 3, grp = blockIdx.x & 7;   // grp covers out rows [grp*32, +32)
    int tid = threadIdx.x;
    for (int i = tid; i < 8192; i += 256) sg[i >> 6][i & 63] = g_gx[b*8192 + i];
    __syncthreads();
    int p = tid & 63, qq = tid >> 2;   // unused qq; recompute below
    int q4 = tid >> 6;                 // 0..3, each handles 8 out-rows
    #pragma unroll
    for (int u = 0; u < 8; u++) {
        int co = grp*32 + q4*8 + u;    // 0..255 (0..127 = k, 128..255 = v)
        const float* wr = kvw + (size_t)co * 128;
        float a = 0.f;
        #pragma unroll 8
        for (int cc = 0; cc < 128; cc++) a = fmaf(sg[cc][p], __ldg(&wr[cc]), a);
        if (co < 128) g_k16[(b*64 + p)*128 + co]        = __float2half(a);
        else          g_v1t[(b*128 + (co - 128))*64 + p] = __float2half(a);
    }
    (void)qq;
}

// ---------------- fused window kernel ----------------------------------------
#define AST 136    // half stride (s_a, s_b)
#define VST 72     // half stride (s_vt)
#define WST 132    // float stride (s_wf)
#define PST 68     // float stride (s_p)
#define OFF_WF 0
#define OFF_P  33792
#define OFF_A  51200
#define OFF_B  68608
#define OFF_VT 86016
#define SMEMB  104448

// C[4][2][4] = A(64x128 @ ua) @ W^T via fragment-major weights
__device__ __forceinline__ void gemmW(uint32_t ua, const uint2* __restrict__ wfr,
                                      int lane, int wp, float C[4][2][4]) {
    #pragma unroll
    for (int mt = 0; mt < 4; mt++)
        #pragma unroll
        for (int nt = 0; nt < 2; nt++)
            #pragma unroll
            for (int k = 0; k < 4; k++) C[mt][nt][k] = 0.f;
    uint32_t ab = ua + (((lane & 15)*AST + ((lane & 16) >> 1)) << 1);
    #pragma unroll
    for (int kb = 0; kb < 8; kb++) {
        uint2 w0 = __ldg(&wfr[(kb*16 + 2*wp    )*32 + lane]);
        uint2 w1 = __ldg(&wfr[(kb*16 + 2*wp + 1)*32 + lane]);
        #pragma unroll
        for (int mt = 0; mt < 4; mt++) {
            uint32_t a0, a1, a2, a3;
            LDSM4(a0, a1, a2, a3, ab + mt*(AST*32) + kb*32);
            mma16(C[mt][0], a0, a1, a2, a3, w0.x, w0.y);
            mma16(C[mt][1], a0, a1, a2, a3, w1.x, w1.y);
        }
    }
}

// Cq[4][4] = Q(ua) @ K(ub)^T, warp strip of 8 cols
__device__ __forceinline__ void gemmQK(uint32_t ua, uint32_t ub,
                                       int lane, int wp, float Cq[4][4]) {
    #pragma unroll
    for (int mt = 0; mt < 4; mt++)
        #pragma unroll
        for (int k = 0; k < 4; k++) Cq[mt][k] = 0.f;
    uint32_t ab = ua + (((lane & 15)*AST + ((lane & 16) >> 1)) << 1);
    uint32_t bb = ub + (((wp*8 + (lane & 7))*AST + (lane >> 3)*8) << 1);
    #pragma unroll
    for (int kp = 0; kp < 4; kp++) {
        uint32_t b0, b1, b2, b3;
        LDSM4(b0, b1, b2, b3, bb + kp*64);
        #pragma unroll
        for (int mt = 0; mt < 4; mt++) {
            uint32_t a0, a1, a2, a3;
            LDSM4(a0, a1, a2, a3, ab + mt*(AST*32) + kp*64);
            mma16(Cq[mt], a0, a1, a2, a3, b0, b1);
            LDSM4(a0, a1, a2, a3, ab + mt*(AST*32) + kp*64 + 32);
            mma16(Cq[mt], a0, a1, a2, a3, b2, b3);
        }
    }
}

// C[4][2][4] = attn(ua cols 0..63) @ V(uvt transposed), K=64
__device__ __forceinline__ void gemmAV(uint32_t ua, uint32_t uvt,
                                       int lane, int wp, float C[4][2][4]) {
    #pragma unroll
    for (int mt = 0; mt < 4; mt++)
        #pragma unroll
        for (int nt = 0; nt < 2; nt++)
            #pragma unroll
            for (int k = 0; k < 4; k++) C[mt][nt][k] = 0.f;
    uint32_t ab = ua + (((lane & 15)*AST + ((lane & 16) >> 1)) << 1);
    uint32_t vb = uvt + (((wp*16 + (lane & 7) + ((lane & 16) >> 1))*VST + (lane & 8)) << 1);
    #pragma unroll
    for (int kb = 0; kb < 4; kb++) {
        uint32_t b0, b1, b2, b3;
        LDSM4(b0, b1, b2, b3, vb + kb*32);
        #pragma unroll
        for (int mt = 0; mt < 4; mt++) {
            uint32_t a0, a1, a2, a3;
            LDSM4(a0, a1, a2, a3, ab + mt*(AST*32) + kb*32);
            mma16(C[mt][0], a0, a1, a2, a3, b0, b1);
            mma16(C[mt][1], a0, a1, a2, a3, b2, b3);
        }
    }
}

__global__ void __launch_bounds__(256) window_kernel(
    const float* __restrict__ fm,
    const float* __restrict__ lb, const float* __restrict__ pb,
    float* __restrict__ out)
{
    extern __shared__ char sm[];
    float*  s_wf = (float*) (sm + OFF_WF);
    float*  s_p  = (float*) (sm + OFF_P);
    __half* s_a  = (__half*)(sm + OFF_A);
    __half* s_b  = (__half*)(sm + OFF_B);
    __half* s_vt = (__half*)(sm + OFF_VT);
    uint32_t ua  = smem_u32(s_a);
    uint32_t ub  = smem_u32(s_b);
    uint32_t uvt = smem_u32(s_vt);

    int tid = threadIdx.x, wp = tid >> 5, lane = tid & 31;
    int g = lane >> 2, t = lane & 3;
    int idx = blockIdx.x;
    int b = idx / NWF;
    int w = g_sel[idx];
    int wh = w >> 6, ww = w & 63;
    const size_t plane = (size_t)NH * NW;
    const float* fbase = fm  + (size_t)b*NC*plane + (size_t)(wh*8)*NW + ww*8;
    float*       obase = out + (size_t)b*NC*plane + (size_t)(wh*8)*NW + ww*8;

    // gather window (fp32 master + fp16 mirror) + stage k1 / v1t
    {
        int col = tid & 7, r = (tid >> 3) & 7, c0 = tid >> 6;
        int t8 = r*8 + col;
        #pragma unroll
        for (int k = 0; k < 32; k++) {
            int c = c0 + 4*k;
            float v = fbase[(size_t)c*plane + r*NW + col];
            s_wf[t8*WST + c] = v;
            s_a[t8*AST + c] = __float2half(v);
        }
        const uint4* kg = (const uint4*)(g_k16 + b*8192);
        const uint4* vg = (const uint4*)(g_v1t + b*8192);
        for (int i = tid; i < 1024; i += 256) {
            int row = i >> 4, c16 = i & 15;
            *(uint4*)(s_b + row*AST + c16*8) = kg[row*16 + c16];
        }
        for (int i = tid; i < 1024; i += 256) {
            int row = i >> 3, c8 = i & 7;
            *(uint4*)(s_vt + row*VST + c8*8) = vg[row*8 + c8];
        }
    }
    __syncthreads();

    float C[4][2][4];
    float Cq[4][4];

    #define FOR_FRAG for (int mt = 0; mt < 4; mt++) for (int nt = 0; nt < 2; nt++)
    #define R0 (mt*16 + g)
    #define R1 (mt*16 + g + 8)
    #define CL (wp*16 + nt*8 + 2*t)

    // ---- q1 = wf @ Wqg^T ----
    gemmW(ua, g_wfrag + MAT_QG*4096, lane, wp, C);
    __syncthreads();
    FOR_FRAG {
        *(uint32_t*)(s_a + R0*AST + CL) = h2u(C[mt][nt][0], C[mt][nt][1]);
        *(uint32_t*)(s_a + R1*AST + CL) = h2u(C[mt][nt][2], C[mt][nt][3]);
    }
    __syncthreads();

    // ---- logits1 = q1 @ k1^T ----
    gemmQK(ua, ub, lane, wp, Cq);
    #pragma unroll
    for (int mt = 0; mt < 4; mt++) {
        int cc = wp*8 + 2*t;
        s_p[(mt*16+g)*PST + cc]     = Cq[mt][0]*SCALE;
        s_p[(mt*16+g)*PST + cc+1]   = Cq[mt][1]*SCALE;
        s_p[(mt*16+g+8)*PST + cc]   = Cq[mt][2]*SCALE;
        s_p[(mt*16+g+8)*PST + cc+1] = Cq[mt][3]*SCALE;
    }
    __syncthreads();

    // ---- softmax1 -> s_a cols 0..63 (half) ----
    {
        int row = tid >> 2, q = tid & 3;
        float* pr = s_p + row*PST + q*16;
        float m = -1e30f, v[16];
        #pragma unroll
        for (int k = 0; k < 16; k++) { v[k] = pr[k]; m = fmaxf(m, v[k]); }
        m = fmaxf(m, __shfl_xor_sync(0xffffffffu, m, 1));
        m = fmaxf(m, __shfl_xor_sync(0xffffffffu, m, 2));
        float s = 0.f;
        #pragma unroll
        for (int k = 0; k < 16; k++) { v[k] = __expf(v[k] - m); s += v[k]; }
        s += __shfl_xor_sync(0xffffffffu, s, 1);
        s += __shfl_xor_sync(0xffffffffu, s, 2);
        float inv = 1.0f / s;
        #pragma unroll
        for (int u = 0; u < 8; u++)
            *(uint32_t*)(s_a + row*AST + q*16 + 2*u) = h2u(v[2*u]*inv, v[2*u+1]*inv);
    }
    __syncthreads();

    // ---- av1 = attn @ v1 ; wf += av1 ----
    gemmAV(ua, uvt, lane, wp, C);
    __syncthreads();
    FOR_FRAG {
        float f0 = s_wf[R0*WST + CL]   + C[mt][nt][0];
        float f1 = s_wf[R0*WST + CL+1] + C[mt][nt][1];
        float f2 = s_wf[R1*WST + CL]   + C[mt][nt][2];
        float f3 = s_wf[R1*WST + CL+1] + C[mt][nt][3];
        s_wf[R0*WST + CL] = f0; s_wf[R0*WST + CL+1] = f1;
        s_wf[R1*WST + CL] = f2; s_wf[R1*WST + CL+1] = f3;
        *(uint32_t*)(s_a + R0*AST + CL) = h2u(f0, f1);
        *(uint32_t*)(s_a + R1*AST + CL) = h2u(f2, f3);
    }
    __syncthreads();

    // ---- MLP1: wf += gelu(wf @ lw^T + lb) ----
    gemmW(ua, g_wfrag + MAT_LIN*4096, lane, wp, C);
    __syncthreads();
    FOR_FRAG {
        float b0 = __ldg(&lb[CL]), b1 = __ldg(&lb[CL+1]);
        float f0 = s_wf[R0*WST + CL]   + gelu_fast(C[mt][nt][0] + b0);
        float f1 = s_wf[R0*WST + CL+1] + gelu_fast(C[mt][nt][1] + b1);
        float f2 = s_wf[R1*WST + CL]   + gelu_fast(C[mt][nt][2] + b0);
        float f3 = s_wf[R1*WST + CL+1] + gelu_fast(C[mt][nt][3] + b1);
        s_wf[R0*WST + CL] = f0; s_wf[R0*WST + CL+1] = f1;
        s_wf[R1*WST + CL] = f2; s_wf[R1*WST + CL+1] = f3;
        *(uint32_t*)(s_a + R0*AST + CL) = h2u(f0, f1);
        *(uint32_t*)(s_a + R1*AST + CL) = h2u(f2, f3);
    }
    __syncthreads();

    // ---- self-attention projections ----
    gemmW(ua, g_wfrag + MAT_K2*4096, lane, wp, C);
    FOR_FRAG {
        *(uint32_t*)(s_b + R0*AST + CL) = h2u(C[mt][nt][0], C[mt][nt][1]);
        *(uint32_t*)(s_b + R1*AST + CL) = h2u(C[mt][nt][2], C[mt][nt][3]);
    }
    gemmW(ua, g_wfrag + MAT_V2*4096, lane, wp, C);
    FOR_FRAG {
        s_vt[(CL  )*VST + R0] = __float2half(C[mt][nt][0]);
        s_vt[(CL+1)*VST + R0] = __float2half(C[mt][nt][1]);
        s_vt[(CL  )*VST + R1] = __float2half(C[mt][nt][2]);
        s_vt[(CL+1)*VST + R1] = __float2half(C[mt][nt][3]);
    }
    gemmW(ua, g_wfrag + MAT_Q2*4096, lane, wp, C);
    __syncthreads();
    FOR_FRAG {
        *(uint32_t*)(s_a + R0*AST + CL) = h2u(C[mt][nt][0], C[mt][nt][1]);
        *(uint32_t*)(s_a + R1*AST + CL) = h2u(C[mt][nt][2], C[mt][nt][3]);
    }
    __syncthreads();

    // ---- logits2 = q2 @ k2^T ----
    gemmQK(ua, ub, lane, wp, Cq);
    #pragma unroll
    for (int mt = 0; mt < 4; mt++) {
        int cc = wp*8 + 2*t;
        s_p[(mt*16+g)*PST + cc]     = Cq[mt][0]*SCALE;
        s_p[(mt*16+g)*PST + cc+1]   = Cq[mt][1]*SCALE;
        s_p[(mt*16+g+8)*PST + cc]   = Cq[mt][2]*SCALE;
        s_p[(mt*16+g+8)*PST + cc+1] = Cq[mt][3]*SCALE;
    }
    __syncthreads();
    {
        int row = tid >> 2, q = tid & 3;
        float* pr = s_p + row*PST + q*16;
        float m = -1e30f, v[16];
        #pragma unroll
        for (int k = 0; k < 16; k++) { v[k] = pr[k]; m = fmaxf(m, v[k]); }
        m = fmaxf(m, __shfl_xor_sync(0xffffffffu, m, 1));
        m = fmaxf(m, __shfl_xor_sync(0xffffffffu, m, 2));
        float s = 0.f;
        #pragma unroll
        for (int k = 0; k < 16; k++) { v[k] = __expf(v[k] - m); s += v[k]; }
        s += __shfl_xor_sync(0xffffffffu, s, 1);
        s += __shfl_xor_sync(0xffffffffu, s, 2);
        float inv = 1.0f / s;
        #pragma unroll
        for (int u = 0; u < 8; u++)
            *(uint32_t*)(s_a + row*AST + q*16 + 2*u) = h2u(v[2*u]*inv, v[2*u+1]*inv);
    }
    __syncthreads();

    // ---- av2 = attn @ v2 -> s_b (half) ----
    gemmAV(ua, uvt, lane, wp, C);
    FOR_FRAG {
        *(uint32_t*)(s_b + R0*AST + CL) = h2u(C[mt][nt][0], C[mt][nt][1]);
        *(uint32_t*)(s_b + R1*AST + CL) = h2u(C[mt][nt][2], C[mt][nt][3]);
    }
    __syncthreads();

    // ---- scrambled residual: wf[i][j] += av[j%64][2i + j/64] ----
    #pragma unroll
    for (int k = 0; k < 32; k++) {
        int id2 = tid + 256*k;
        int i = id2 >> 7, j = id2 & 127;
        float f = s_wf[i*WST + j] + __half2float(s_b[(j & 63)*AST + 2*i + (j >> 6)]);
        s_wf[i*WST + j] = f;
        s_a[i*AST + j] = __float2half(f);
    }
    __syncthreads();

    // ---- MLP2: wf += gelu(wf @ pw^T + pb) ----
    gemmW(ua, g_wfrag + MAT_PR*4096, lane, wp, C);
    __syncthreads();
    FOR_FRAG {
        float b0 = __ldg(&pb[CL]), b1 = __ldg(&pb[CL+1]);
        s_wf[R0*WST + CL]   += gelu_fast(C[mt][nt][0] + b0);
        s_wf[R0*WST + CL+1] += gelu_fast(C[mt][nt][1] + b1);
        s_wf[R1*WST + CL]   += gelu_fast(C[mt][nt][2] + b0);
        s_wf[R1*WST + CL+1] += gelu_fast(C[mt][nt][3] + b1);
    }
    __syncthreads();

    // ---- scatter ----
    {
        int col = tid & 7, r = (tid >> 3) & 7, c0 = tid >> 6;
        int t8 = r*8 + col;
        #pragma unroll
        for (int k = 0; k < 32; k++) {
            int c = c0 + 4*k;
            obase[(size_t)c*plane + r*NW + col] = s_wf[t8*WST + c];
        }
    }
    #undef FOR_FRAG
    #undef R0
    #undef R1
    #undef CL
}

// ---------------- launch ------------------------------------------------------
extern "C" void kernel_launch(void* const* d_in, const int* in_sizes, int n_in,
                              void* d_out, int out_size) {
    const float* fm   = (const float*)d_in[0];
    const float* unc  = (const float*)d_in[1];
    const float* qgw  = (const float*)d_in[2];
    const float* kvw  = (const float*)d_in[3];
    const float* lw   = (const float*)d_in[4];
    const float* lb   = (const float*)d_in[5];
    const float* qkvw = (const float*)d_in[6];
    const float* pw   = (const float*)d_in[7];
    const float* pb   = (const float*)d_in[8];
    float* out = (float*)d_out;

    cudaFuncSetAttribute(window_kernel,
                         cudaFuncAttributeMaxDynamicSharedMemorySize, SMEMB);

    wprep_kernel<<<96, 256>>>(qgw, lw, qkvw, pw);
    scores_kernel<<<1024, 256>>>(unc);
    select_kernel<<<8, 1024>>>();
    copy_pool_kernel<<<NB*NC*8, 512>>>((const float4*)fm, (float4*)out);
    kv_kernel<<<16, 256>>>(kvw);
    window_kernel<<<NSEL, 256, SMEMB>>>(fm, lb, pb, out);
}

// round 11
// speedup vs baseline: 1.2469x; 1.0374x over previous
#include <cuda_runtime.h>
#include <cuda_fp16.h>
#include <math.h>
#include <stdint.h>

#define NB    2
#define NC    128
#define NH    512
#define NW    512
#define NWIN  4096
#define NWF   1228
#define NSEL  (NB*NWF)
#define SCALE 0.08838834764831845f

// ---------------- static device scratch -------------------------------------
__device__ float g_score[NB*NWIN];
__device__ int   g_sel[NB*NWF];
__device__ int   g_cnt[NB];
__device__ unsigned char g_flag[NB*NWIN];
__device__ float g_gx[NB*NC*64];
__device__ __align__(16) uint2  g_wfrag[6*4096];        // fragment-major weights
__device__ __align__(16) __half g_k16[NB*64*128];       // cross-attn K row-major
__device__ __align__(16) __half g_v1t[NB*128*64];       // cross-attn V transposed

#define MAT_QG 0
#define MAT_LIN 1
#define MAT_Q2 2
#define MAT_K2 3
#define MAT_V2 4
#define MAT_PR 5

// ---------------- helpers ----------------------------------------------------
__device__ __forceinline__ uint32_t h2u(float a, float b) {
    __half2 h = __floats2half2_rn(a, b);
    return reinterpret_cast<uint32_t&>(h);
}
__device__ __forceinline__ void mma16(float* c, uint32_t a0, uint32_t a1,
                                      uint32_t a2, uint32_t a3,
                                      uint32_t b0, uint32_t b1) {
    asm volatile("mma.sync.aligned.m16n8k16.row.col.f32.f16.f16.f32 "
                 "{%0,%1,%2,%3}, {%4,%5,%6,%7}, {%8,%9}, {%0,%1,%2,%3};"
                 : "+f"(c[0]), "+f"(c[1]), "+f"(c[2]), "+f"(c[3])
                 : "r"(a0), "r"(a1), "r"(a2), "r"(a3), "r"(b0), "r"(b1));
}
#define LDSM4(r0, r1, r2, r3, addr) \
    asm volatile("ldmatrix.sync.aligned.m8n8.x4.shared.b16 {%0,%1,%2,%3}, [%4];" \
                 : "=r"(r0), "=r"(r1), "=r"(r2), "=r"(r3) : "r"(addr))
__device__ __forceinline__ uint32_t smem_u32(const void* p) {
    uint32_t a;
    asm("{ .reg .u64 t; cvta.to.shared.u64 t, %1; cvt.u32.u64 %0, t; }" : "=r"(a) : "l"(p));
    return a;
}
// fast GELU: 0.5x(1+tanh(0.79788456x + 0.03567741x^3)) with HW tanh
__device__ __forceinline__ float gelu_fast(float x) {
    float u = fmaf(0.0356774081f * x, x * x, 0.7978845608f * x);
    float th;
    asm("tanh.approx.f32 %0, %1;" : "=f"(th) : "f"(u));
    return 0.5f * x * (1.0f + th);
}

// ---------------- prep kernels ----------------------------------------------
__global__ void wprep_kernel(const float* __restrict__ qgw, const float* __restrict__ lw,
                             const float* __restrict__ qkvw, const float* __restrict__ pw) {
    int i = blockIdx.x * 256 + threadIdx.x;          // 24576
    int mat = i >> 12, r = i & 4095;
    int kb = r >> 9, n8 = (r >> 5) & 15, lane = r & 31;
    int g = lane >> 2, t = lane & 3;
    int n = n8*8 + g, k = kb*16 + 2*t;
    const float* W = (mat == 0) ? qgw : (mat == 1) ? lw
                   : (mat <= 4) ? qkvw + (mat - 2)*16384 : pw;
    const float* row = W + n*128;
    uint2 o;
    o.x = h2u(row[k],   row[k+1]);
    o.y = h2u(row[k+8], row[k+9]);
    g_wfrag[i] = o;
}

__global__ void scores_kernel(const float* __restrict__ unc) {
    if (blockIdx.x == 0 && threadIdx.x < NB) g_cnt[threadIdx.x] = 0;
    int gw = blockIdx.x * 8 + (threadIdx.x >> 5);
    int lane = threadIdx.x & 31;
    if (gw >= NB*NWIN) return;
    if (lane == 0) g_flag[gw] = 0;
    int b = gw / NWIN, w = gw % NWIN;
    int wh = w >> 6, ww = w & 63;
    const float* base = unc + ((size_t)b*NH + wh*8)*NW + ww*8;
    int r0 = lane >> 3, c0 = lane & 7;
    double s = (double)base[r0*NW + c0] + (double)base[(r0+4)*NW + c0];
    #pragma unroll
    for (int o = 16; o; o >>= 1) s += __shfl_down_sync(0xffffffffu, s, o);
    if (lane == 0) g_score[gw] = (float)(s * (1.0/64.0));
}

__global__ void select_kernel() {
    __shared__ float s_sc[NWIN];
    int b = blockIdx.x >> 2, part = blockIdx.x & 3;
    const float* sc = g_score + b*NWIN;
    for (int i = threadIdx.x; i < NWIN; i += 1024) s_sc[i] = sc[i];
    __syncthreads();
    int w = part*1024 + threadIdx.x;
    float my = s_sc[w];
    int rank = 0;
    #pragma unroll 8
    for (int j = 0; j < NWIN; j++) {
        float v = s_sc[j];
        rank += (v > my) || (v == my && j < w);
    }
    if (rank < NWF) {
        int pos = atomicAdd(&g_cnt[b], 1);
        g_sel[b*NWF + pos] = w;
        g_flag[b*NWIN + w] = 1;
    }
}

// fused copy(+skip selected) + 8x8 grid average pool, float4 (reads fm once)
__global__ void copy_pool_kernel(const float4* __restrict__ fm4, float4* __restrict__ out4) {
    __shared__ float sp[512];
    __shared__ unsigned char sfl[512];
    int bci = blockIdx.x, ci = bci & 7, bc = bci >> 3;
    int b = bc >> 7;
    const float4* base = fm4  + ((size_t)bc*NH + ci*64)*(NW/4);
    float4*       ob   = out4 + ((size_t)bc*NH + ci*64)*(NW/4);
    int t = threadIdx.x;
    // flags for this 64-row band: wh in [ci*8, ci*8+8), ww 0..63
    {
        const unsigned char* fl = g_flag + b*NWIN + ci*8*64;
        if (t < 512) sfl[t] = fl[t];
    }
    __syncthreads();
    float acc = 0.f;
    #pragma unroll 4
    for (int it = 0; it < 16; it++) {
        int i4 = it*512 + t;               // row = i4>>7 (0..63), col4 = i4 & 127
        float4 v = base[i4];
        int r = i4 >> 7, c4 = i4 & 127;
        if (!sfl[(r >> 3)*64 + (c4 >> 1)]) ob[i4] = v;
        acc += (v.x + v.y) + (v.z + v.w);
    }
    int cell = (t & 127) >> 4;
    int sub  = (t >> 7) * 16 + (t & 15);
    sp[cell*64 + sub] = acc;
    __syncthreads();
    int grp = t >> 6, i = t & 63;
    for (int off = 32; off >= 1; off >>= 1) {
        if (i < off) sp[grp*64 + i] += sp[grp*64 + i + off];
        __syncthreads();
    }
    if (i == 0) g_gx[bc*64 + ci*8 + grp] = sp[grp*64] * (1.0f/4096.0f);
}

// k1, v1 for cross attention: 16 blocks, g staged in smem once
__global__ void kv_kernel(const float* __restrict__ kvw) {
    __shared__ float sg[128][65];
    int b = blockIdx.x >> 3, grp = blockIdx.x & 7;
    int tid = threadIdx.x;
    for (int i = tid; i < 8192; i += 256) sg[i >> 6][i & 63] = g_gx[b*8192 + i];
    __syncthreads();
    int p = tid & 63, q4 = tid >> 6;
    #pragma unroll
    for (int u = 0; u < 8; u++) {
        int co = grp*32 + q4*8 + u;        // 0..255 (0..127 = k, 128..255 = v)
        const float* wr = kvw + (size_t)co * 128;
        float a = 0.f;
        #pragma unroll 8
        for (int cc = 0; cc < 128; cc++) a = fmaf(sg[cc][p], __ldg(&wr[cc]), a);
        if (co < 128) g_k16[(b*64 + p)*128 + co]         = __float2half(a);
        else          g_v1t[(b*128 + (co - 128))*64 + p] = __float2half(a);
    }
}

// ---------------- fused window kernel ----------------------------------------
#define AST 136    // half stride (s_a, s_b)
#define VST 72     // half stride (s_vt)
#define WST 132    // float stride (s_wf)
#define PST 68     // float stride (s_p)
#define OFF_WF 0
#define OFF_P  33792
#define OFF_A  51200
#define OFF_B  68608
#define OFF_VT 86016
#define SMEMB  104448

// C[4][2][4] = A(64x128 @ ua) @ W^T via fragment-major weights
__device__ __forceinline__ void gemmW(uint32_t ua, const uint2* __restrict__ wfr,
                                      int lane, int wp, float C[4][2][4]) {
    #pragma unroll
    for (int mt = 0; mt < 4; mt++)
        #pragma unroll
        for (int nt = 0; nt < 2; nt++)
            #pragma unroll
            for (int k = 0; k < 4; k++) C[mt][nt][k] = 0.f;
    uint32_t ab = ua + (((lane & 15)*AST + ((lane & 16) >> 1)) << 1);
    #pragma unroll
    for (int kb = 0; kb < 8; kb++) {
        uint2 w0 = __ldg(&wfr[(kb*16 + 2*wp    )*32 + lane]);
        uint2 w1 = __ldg(&wfr[(kb*16 + 2*wp + 1)*32 + lane]);
        #pragma unroll
        for (int mt = 0; mt < 4; mt++) {
            uint32_t a0, a1, a2, a3;
            LDSM4(a0, a1, a2, a3, ab + mt*(AST*32) + kb*32);
            mma16(C[mt][0], a0, a1, a2, a3, w0.x, w0.y);
            mma16(C[mt][1], a0, a1, a2, a3, w1.x, w1.y);
        }
    }
}

// Cq[4][4] = Q(ua) @ K(ub)^T, warp strip of 8 cols
__device__ __forceinline__ void gemmQK(uint32_t ua, uint32_t ub,
                                       int lane, int wp, float Cq[4][4]) {
    #pragma unroll
    for (int mt = 0; mt < 4; mt++)
        #pragma unroll
        for (int k = 0; k < 4; k++) Cq[mt][k] = 0.f;
    uint32_t ab = ua + (((lane & 15)*AST + ((lane & 16) >> 1)) << 1);
    uint32_t bb = ub + (((wp*8 + (lane & 7))*AST + (lane >> 3)*8) << 1);
    #pragma unroll
    for (int kp = 0; kp < 4; kp++) {
        uint32_t b0, b1, b2, b3;
        LDSM4(b0, b1, b2, b3, bb + kp*64);
        #pragma unroll
        for (int mt = 0; mt < 4; mt++) {
            uint32_t a0, a1, a2, a3;
            LDSM4(a0, a1, a2, a3, ab + mt*(AST*32) + kp*64);
            mma16(Cq[mt], a0, a1, a2, a3, b0, b1);
            LDSM4(a0, a1, a2, a3, ab + mt*(AST*32) + kp*64 + 32);
            mma16(Cq[mt], a0, a1, a2, a3, b2, b3);
        }
    }
}

// C[4][2][4] = attn(ua cols 0..63) @ V(uvt transposed), K=64
__device__ __forceinline__ void gemmAV(uint32_t ua, uint32_t uvt,
                                       int lane, int wp, float C[4][2][4]) {
    #pragma unroll
    for (int mt = 0; mt < 4; mt++)
        #pragma unroll
        for (int nt = 0; nt < 2; nt++)
            #pragma unroll
            for (int k = 0; k < 4; k++) C[mt][nt][k] = 0.f;
    uint32_t ab = ua + (((lane & 15)*AST + ((lane & 16) >> 1)) << 1);
    uint32_t vb = uvt + (((wp*16 + (lane & 7) + ((lane & 16) >> 1))*VST + (lane & 8)) << 1);
    #pragma unroll
    for (int kb = 0; kb < 4; kb++) {
        uint32_t b0, b1, b2, b3;
        LDSM4(b0, b1, b2, b3, vb + kb*32);
        #pragma unroll
        for (int mt = 0; mt < 4; mt++) {
            uint32_t a0, a1, a2, a3;
            LDSM4(a0, a1, a2, a3, ab + mt*(AST*32) + kb*32);
            mma16(C[mt][0], a0, a1, a2, a3, b0, b1);
            mma16(C[mt][1], a0, a1, a2, a3, b2, b3);
        }
    }
}

__global__ void __launch_bounds__(256, 2) window_kernel(
    const float* __restrict__ fm,
    const float* __restrict__ lb, const float* __restrict__ pb,
    float* __restrict__ out)
{
    extern __shared__ char sm[];
    float*  s_wf = (float*) (sm + OFF_WF);
    float*  s_p  = (float*) (sm + OFF_P);
    __half* s_a  = (__half*)(sm + OFF_A);
    __half* s_b  = (__half*)(sm + OFF_B);
    __half* s_vt = (__half*)(sm + OFF_VT);
    uint32_t ua  = smem_u32(s_a);
    uint32_t ub  = smem_u32(s_b);
    uint32_t uvt = smem_u32(s_vt);

    int tid = threadIdx.x, wp = tid >> 5, lane = tid & 31;
    int g = lane >> 2, t = lane & 3;
    int idx = blockIdx.x;
    int b = idx / NWF;
    int w = g_sel[idx];
    int wh = w >> 6, ww = w & 63;
    const size_t plane = (size_t)NH * NW;
    const float* fbase = fm  + (size_t)b*NC*plane + (size_t)(wh*8)*NW + ww*8;
    float*       obase = out + (size_t)b*NC*plane + (size_t)(wh*8)*NW + ww*8;

    // gather window (fp32 master + fp16 mirror) + stage k1 / v1t
    {
        int col = tid & 7, r = (tid >> 3) & 7, c0 = tid >> 6;
        int t8 = r*8 + col;
        #pragma unroll
        for (int k = 0; k < 32; k++) {
            int c = c0 + 4*k;
            float v = fbase[(size_t)c*plane + r*NW + col];
            s_wf[t8*WST + c] = v;
            s_a[t8*AST + c] = __float2half(v);
        }
        const uint4* kg = (const uint4*)(g_k16 + b*8192);
        const uint4* vg = (const uint4*)(g_v1t + b*8192);
        for (int i = tid; i < 1024; i += 256) {
            int row = i >> 4, c16 = i & 15;
            *(uint4*)(s_b + row*AST + c16*8) = kg[row*16 + c16];
        }
        for (int i = tid; i < 1024; i += 256) {
            int row = i >> 3, c8 = i & 7;
            *(uint4*)(s_vt + row*VST + c8*8) = vg[row*8 + c8];
        }
    }
    __syncthreads();

    float C[4][2][4];
    float Cq[4][4];

    #define FOR_FRAG for (int mt = 0; mt < 4; mt++) for (int nt = 0; nt < 2; nt++)
    #define R0 (mt*16 + g)
    #define R1 (mt*16 + g + 8)
    #define CL (wp*16 + nt*8 + 2*t)

    // ---- q1 = wf @ Wqg^T ----
    gemmW(ua, g_wfrag + MAT_QG*4096, lane, wp, C);
    __syncthreads();
    FOR_FRAG {
        *(uint32_t*)(s_a + R0*AST + CL) = h2u(C[mt][nt][0], C[mt][nt][1]);
        *(uint32_t*)(s_a + R1*AST + CL) = h2u(C[mt][nt][2], C[mt][nt][3]);
    }
    __syncthreads();

    // ---- logits1 = q1 @ k1^T ----
    gemmQK(ua, ub, lane, wp, Cq);
    #pragma unroll
    for (int mt = 0; mt < 4; mt++) {
        int cc = wp*8 + 2*t;
        s_p[(mt*16+g)*PST + cc]     = Cq[mt][0]*SCALE;
        s_p[(mt*16+g)*PST + cc+1]   = Cq[mt][1]*SCALE;
        s_p[(mt*16+g+8)*PST + cc]   = Cq[mt][2]*SCALE;
        s_p[(mt*16+g+8)*PST + cc+1] = Cq[mt][3]*SCALE;
    }
    __syncthreads();

    // ---- softmax1 -> s_a cols 0..63 (half) ----
    {
        int row = tid >> 2, q = tid & 3;
        float* pr = s_p + row*PST + q*16;
        float m = -1e30f, v[16];
        #pragma unroll
        for (int k = 0; k < 16; k++) { v[k] = pr[k]; m = fmaxf(m, v[k]); }
        m = fmaxf(m, __shfl_xor_sync(0xffffffffu, m, 1));
        m = fmaxf(m, __shfl_xor_sync(0xffffffffu, m, 2));
        float s = 0.f;
        #pragma unroll
        for (int k = 0; k < 16; k++) { v[k] = __expf(v[k] - m); s += v[k]; }
        s += __shfl_xor_sync(0xffffffffu, s, 1);
        s += __shfl_xor_sync(0xffffffffu, s, 2);
        float inv = 1.0f / s;
        #pragma unroll
        for (int u = 0; u < 8; u++)
            *(uint32_t*)(s_a + row*AST + q*16 + 2*u) = h2u(v[2*u]*inv, v[2*u+1]*inv);
    }
    __syncthreads();

    // ---- av1 = attn @ v1 ; wf += av1 ----
    gemmAV(ua, uvt, lane, wp, C);
    __syncthreads();
    FOR_FRAG {
        float f0 = s_wf[R0*WST + CL]   + C[mt][nt][0];
        float f1 = s_wf[R0*WST + CL+1] + C[mt][nt][1];
        float f2 = s_wf[R1*WST + CL]   + C[mt][nt][2];
        float f3 = s_wf[R1*WST + CL+1] + C[mt][nt][3];
        s_wf[R0*WST + CL] = f0; s_wf[R0*WST + CL+1] = f1;
        s_wf[R1*WST + CL] = f2; s_wf[R1*WST + CL+1] = f3;
        *(uint32_t*)(s_a + R0*AST + CL) = h2u(f0, f1);
        *(uint32_t*)(s_a + R1*AST + CL) = h2u(f2, f3);
    }
    __syncthreads();

    // ---- MLP1: wf += gelu(wf @ lw^T + lb) ----
    gemmW(ua, g_wfrag + MAT_LIN*4096, lane, wp, C);
    __syncthreads();
    FOR_FRAG {
        float b0 = __ldg(&lb[CL]), b1 = __ldg(&lb[CL+1]);
        float f0 = s_wf[R0*WST + CL]   + gelu_fast(C[mt][nt][0] + b0);
        float f1 = s_wf[R0*WST + CL+1] + gelu_fast(C[mt][nt][1] + b1);
        float f2 = s_wf[R1*WST + CL]   + gelu_fast(C[mt][nt][2] + b0);
        float f3 = s_wf[R1*WST + CL+1] + gelu_fast(C[mt][nt][3] + b1);
        s_wf[R0*WST + CL] = f0; s_wf[R0*WST + CL+1] = f1;
        s_wf[R1*WST + CL] = f2; s_wf[R1*WST + CL+1] = f3;
        *(uint32_t*)(s_a + R0*AST + CL) = h2u(f0, f1);
        *(uint32_t*)(s_a + R1*AST + CL) = h2u(f2, f3);
    }
    __syncthreads();

    // ---- self-attention projections ----
    gemmW(ua, g_wfrag + MAT_K2*4096, lane, wp, C);
    FOR_FRAG {
        *(uint32_t*)(s_b + R0*AST + CL) = h2u(C[mt][nt][0], C[mt][nt][1]);
        *(uint32_t*)(s_b + R1*AST + CL) = h2u(C[mt][nt][2], C[mt][nt][3]);
    }
    gemmW(ua, g_wfrag + MAT_V2*4096, lane, wp, C);
    FOR_FRAG {
        s_vt[(CL  )*VST + R0] = __float2half(C[mt][nt][0]);
        s_vt[(CL+1)*VST + R0] = __float2half(C[mt][nt][1]);
        s_vt[(CL  )*VST + R1] = __float2half(C[mt][nt][2]);
        s_vt[(CL+1)*VST + R1] = __float2half(C[mt][nt][3]);
    }
    gemmW(ua, g_wfrag + MAT_Q2*4096, lane, wp, C);
    __syncthreads();
    FOR_FRAG {
        *(uint32_t*)(s_a + R0*AST + CL) = h2u(C[mt][nt][0], C[mt][nt][1]);
        *(uint32_t*)(s_a + R1*AST + CL) = h2u(C[mt][nt][2], C[mt][nt][3]);
    }
    __syncthreads();

    // ---- logits2 = q2 @ k2^T ----
    gemmQK(ua, ub, lane, wp, Cq);
    #pragma unroll
    for (int mt = 0; mt < 4; mt++) {
        int cc = wp*8 + 2*t;
        s_p[(mt*16+g)*PST + cc]     = Cq[mt][0]*SCALE;
        s_p[(mt*16+g)*PST + cc+1]   = Cq[mt][1]*SCALE;
        s_p[(mt*16+g+8)*PST + cc]   = Cq[mt][2]*SCALE;
        s_p[(mt*16+g+8)*PST + cc+1] = Cq[mt][3]*SCALE;
    }
    __syncthreads();
    {
        int row = tid >> 2, q = tid & 3;
        float* pr = s_p + row*PST + q*16;
        float m = -1e30f, v[16];
        #pragma unroll
        for (int k = 0; k < 16; k++) { v[k] = pr[k]; m = fmaxf(m, v[k]); }
        m = fmaxf(m, __shfl_xor_sync(0xffffffffu, m, 1));
        m = fmaxf(m, __shfl_xor_sync(0xffffffffu, m, 2));
        float s = 0.f;
        #pragma unroll
        for (int k = 0; k < 16; k++) { v[k] = __expf(v[k] - m); s += v[k]; }
        s += __shfl_xor_sync(0xffffffffu, s, 1);
        s += __shfl_xor_sync(0xffffffffu, s, 2);
        float inv = 1.0f / s;
        #pragma unroll
        for (int u = 0; u < 8; u++)
            *(uint32_t*)(s_a + row*AST + q*16 + 2*u) = h2u(v[2*u]*inv, v[2*u+1]*inv);
    }
    __syncthreads();

    // ---- av2 = attn @ v2 -> s_b (half) ----
    gemmAV(ua, uvt, lane, wp, C);
    FOR_FRAG {
        *(uint32_t*)(s_b + R0*AST + CL) = h2u(C[mt][nt][0], C[mt][nt][1]);
        *(uint32_t*)(s_b + R1*AST + CL) = h2u(C[mt][nt][2], C[mt][nt][3]);
    }
    __syncthreads();

    // ---- scrambled residual: wf[i][j] += av[j%64][2i + j/64] ----
    #pragma unroll
    for (int k = 0; k < 32; k++) {
        int id2 = tid + 256*k;
        int i = id2 >> 7, j = id2 & 127;
        float f = s_wf[i*WST + j] + __half2float(s_b[(j & 63)*AST + 2*i + (j >> 6)]);
        s_wf[i*WST + j] = f;
        s_a[i*AST + j] = __float2half(f);
    }
    __syncthreads();

    // ---- MLP2: wf += gelu(wf @ pw^T + pb) ----
    gemmW(ua, g_wfrag + MAT_PR*4096, lane, wp, C);
    __syncthreads();
    FOR_FRAG {
        float b0 = __ldg(&pb[CL]), b1 = __ldg(&pb[CL+1]);
        s_wf[R0*WST + CL]   += gelu_fast(C[mt][nt][0] + b0);
        s_wf[R0*WST + CL+1] += gelu_fast(C[mt][nt][1] + b1);
        s_wf[R1*WST + CL]   += gelu_fast(C[mt][nt][2] + b0);
        s_wf[R1*WST + CL+1] += gelu_fast(C[mt][nt][3] + b1);
    }
    __syncthreads();

    // ---- scatter ----
    {
        int col = tid & 7, r = (tid >> 3) & 7, c0 = tid >> 6;
        int t8 = r*8 + col;
        #pragma unroll
        for (int k = 0; k < 32; k++) {
            int c = c0 + 4*k;
            obase[(size_t)c*plane + r*NW + col] = s_wf[t8*WST + c];
        }
    }
    #undef FOR_FRAG
    #undef R0
    #undef R1
    #undef CL
}

// ---------------- launch ------------------------------------------------------
extern "C" void kernel_launch(void* const* d_in, const int* in_sizes, int n_in,
                              void* d_out, int out_size) {
    const float* fm   = (const float*)d_in[0];
    const float* unc  = (const float*)d_in[1];
    const float* qgw  = (const float*)d_in[2];
    const float* kvw  = (const float*)d_in[3];
    const float* lw   = (const float*)d_in[4];
    const float* lb   = (const float*)d_in[5];
    const float* qkvw = (const float*)d_in[6];
    const float* pw   = (const float*)d_in[7];
    const float* pb   = (const float*)d_in[8];
    float* out = (float*)d_out;

    cudaFuncSetAttribute(window_kernel,
                         cudaFuncAttributeMaxDynamicSharedMemorySize, SMEMB);

    wprep_kernel<<<96, 256>>>(qgw, lw, qkvw, pw);
    scores_kernel<<<1024, 256>>>(unc);
    select_kernel<<<8, 1024>>>();
    copy_pool_kernel<<<NB*NC*8, 512>>>((const float4*)fm, (float4*)out);
    kv_kernel<<<16, 256>>>(kvw);
    window_kernel<<<NSEL, 256, SMEMB>>>(fm, lb, pb, out);
}